// round 5
// baseline (speedup 1.0000x reference)
#include <cuda_runtime.h>
#include <math.h>

#define N_ROWS 65536   // 8192 * 8
#define DIM    256
#define KCODES 1024
#define BM     128     // rows per CTA
#define BN     128     // codes per chunk
#define BK     32      // D panel width
#define NCHUNK (KCODES / BN)   // 8
#define NPANEL (DIM / BK)      // 8
#define NBLOCKS (N_ROWS / BM)  // 512

#define POS_INF __builtin_huge_valf()

__device__ float g_norm_e[KCODES];    // ||e_k||^2
__device__ float g_norm_x[N_ROWS];    // ||x_r||^2
__device__ float g_partial[NBLOCKS];

// ---------------------------------------------------------------------------
// Kernel 1a: ||e_k||^2 for all codes
// ---------------------------------------------------------------------------
__global__ void vq_norms_e_kernel(const float* __restrict__ emb) {
    int k = blockIdx.x * blockDim.x + threadIdx.x;
    if (k < KCODES) {
        const float4* e4 = (const float4*)(emb + (size_t)k * DIM);
        float s = 0.0f;
        #pragma unroll 8
        for (int q = 0; q < DIM / 4; q++) {
            float4 v = e4[q];
            s += v.x * v.x + v.y * v.y + v.z * v.z + v.w * v.w;
        }
        g_norm_e[k] = s;
    }
}

// ---------------------------------------------------------------------------
// Kernel 1b: ||x_r||^2 for all rows (one warp per row, coalesced)
// ---------------------------------------------------------------------------
__global__ void vq_norms_x_kernel(const float* __restrict__ lat) {
    int warp = (blockIdx.x * blockDim.x + threadIdx.x) >> 5;
    int lane = threadIdx.x & 31;
    if (warp < N_ROWS) {
        const float4* x4 = (const float4*)(lat + (size_t)warp * DIM);
        float s = 0.0f;
        #pragma unroll
        for (int q = 0; q < 2; q++) {
            float4 v = x4[lane + 32 * q];
            s += v.x * v.x + v.y * v.y + v.z * v.z + v.w * v.w;
        }
        #pragma unroll
        for (int off = 16; off >= 1; off >>= 1)
            s += __shfl_xor_sync(0xffffffffu, s, off);
        if (lane == 0) g_norm_x[warp] = s;
    }
}

// ---------------------------------------------------------------------------
// Kernel 2: fused GEMM + argmin + gather + per-block loss partial
// dist(r,k) = fl32( fl32(||x||^2 + ||e||^2) - 2*dot ) -- replicates the
// reference's fp32 rounding (grid ~ulp(256)); dot computed with two-stage
// accumulation (chains <=32) so our dot error << one grid cell.
// ---------------------------------------------------------------------------
__global__ void __launch_bounds__(256, 1)
vq_main_kernel(const float* __restrict__ lat,
               const float* __restrict__ emb,
               float* __restrict__ out) {
    __shared__ float Xs[BM][BK + 1];
    __shared__ float Es[BN][BK + 1];
    __shared__ float s_nx[BM];
    __shared__ float s_row_min[BM];
    __shared__ int   s_row_idx[BM];
    __shared__ float s_warpsum[8];

    const int tid = threadIdx.x;
    const int tx = tid & 15;         // code sub-index
    const int ty = tid >> 4;         // row sub-index
    const int r0 = blockIdx.x * BM;

    if (tid < BM) {
        s_row_min[tid] = POS_INF;
        s_row_idx[tid] = 0;
        s_nx[tid] = g_norm_x[r0 + tid];
    }

    for (int c = 0; c < NCHUNK; c++) {
        float acc_hi[8][8];
        #pragma unroll
        for (int i = 0; i < 8; i++)
            #pragma unroll
            for (int j = 0; j < 8; j++)
                acc_hi[i][j] = 0.0f;

        for (int p = 0; p < NPANEL; p++) {
            __syncthreads();   // protect Xs/Es from previous iteration's readers
            // load X panel [BM x BK] : 1024 float4, 4 per thread
            #pragma unroll
            for (int t = tid; t < BM * (BK / 4); t += 256) {
                int row = t >> 3;
                int q   = t & 7;
                float4 v = *(const float4*)(lat + (size_t)(r0 + row) * DIM + p * BK + q * 4);
                Xs[row][q * 4 + 0] = v.x;
                Xs[row][q * 4 + 1] = v.y;
                Xs[row][q * 4 + 2] = v.z;
                Xs[row][q * 4 + 3] = v.w;
            }
            // load E panel [BN x BK]
            #pragma unroll
            for (int t = tid; t < BN * (BK / 4); t += 256) {
                int row = t >> 3;
                int q   = t & 7;
                float4 v = *(const float4*)(emb + (size_t)(c * BN + row) * DIM + p * BK + q * 4);
                Es[row][q * 4 + 0] = v.x;
                Es[row][q * 4 + 1] = v.y;
                Es[row][q * 4 + 2] = v.z;
                Es[row][q * 4 + 3] = v.w;
            }
            __syncthreads();

            // panel accumulator (chain length 32)
            float acc[8][8];
            #pragma unroll
            for (int i = 0; i < 8; i++)
                #pragma unroll
                for (int j = 0; j < 8; j++)
                    acc[i][j] = 0.0f;

            #pragma unroll 4
            for (int k = 0; k < BK; k++) {
                float a[8], b[8];
                #pragma unroll
                for (int i = 0; i < 8; i++) a[i] = Xs[ty + 16 * i][k];
                #pragma unroll
                for (int j = 0; j < 8; j++) b[j] = Es[tx + 16 * j][k];
                #pragma unroll
                for (int i = 0; i < 8; i++)
                    #pragma unroll
                    for (int j = 0; j < 8; j++)
                        acc[i][j] = __fmaf_rn(a[i], b[j], acc[i][j]);
            }

            // fold panel into master accumulator (chain length 8)
            #pragma unroll
            for (int i = 0; i < 8; i++)
                #pragma unroll
                for (int j = 0; j < 8; j++)
                    acc_hi[i][j] = __fadd_rn(acc_hi[i][j], acc[i][j]);
        }

        // per-row chunk argmin with the reference's exact fp32 rounding
        #pragma unroll
        for (int i = 0; i < 8; i++) {
            int row = ty + 16 * i;
            float nx = s_nx[row];
            float bv = POS_INF;
            int   bi = 0;
            #pragma unroll
            for (int j = 0; j < 8; j++) {
                int col = c * BN + tx + 16 * j;
                float ne = __ldg(&g_norm_e[col]);
                // dist = fl( fl(nx + ne) - fl(2*dot) ), no contraction
                float s = __fsub_rn(__fadd_rn(nx, ne),
                                    __fmul_rn(2.0f, acc_hi[i][j]));
                if (s < bv) { bv = s; bi = col; }   // ascending col -> first-min
            }
            #pragma unroll
            for (int off = 8; off >= 1; off >>= 1) {
                float ov = __shfl_xor_sync(0xffffffffu, bv, off, 16);
                int   oi = __shfl_xor_sync(0xffffffffu, bi, off, 16);
                if (ov < bv || (ov == bv && oi < bi)) { bv = ov; bi = oi; }
            }
            if (tx == 0) {   // single writer per row; strict < keeps earliest chunk
                if (bv < s_row_min[row]) {
                    s_row_min[row] = bv;
                    s_row_idx[row] = bi;
                }
            }
        }
    }
    __syncthreads();

    // epilogue: gather winning code rows, write output, rescore exact loss
    float lsum = 0.0f;
    const float4* lat4 = (const float4*)lat;
    const float4* emb4 = (const float4*)emb;
    float4*       out4 = (float4*)out;
    #pragma unroll
    for (int t = tid; t < BM * (DIM / 4); t += 256) {
        int row = t >> 6;             // DIM/4 = 64
        int q   = t & 63;
        int code = s_row_idx[row];
        float4 e = emb4[(size_t)code * (DIM / 4) + q];
        float4 x = lat4[(size_t)(r0 + row) * (DIM / 4) + q];
        out4[(size_t)(r0 + row) * (DIM / 4) + q] = e;
        float dx = x.x - e.x, dy = x.y - e.y, dz = x.z - e.z, dw = x.w - e.w;
        lsum += dx * dx + dy * dy + dz * dz + dw * dw;
    }

    // deterministic block reduce
    #pragma unroll
    for (int off = 16; off >= 1; off >>= 1)
        lsum += __shfl_xor_sync(0xffffffffu, lsum, off);
    if ((tid & 31) == 0) s_warpsum[tid >> 5] = lsum;
    __syncthreads();
    if (tid == 0) {
        float tot = 0.0f;
        #pragma unroll
        for (int w = 0; w < 8; w++) tot += s_warpsum[w];
        g_partial[blockIdx.x] = tot;
    }
}

// ---------------------------------------------------------------------------
// Kernel 3: deterministic loss finalize
// ---------------------------------------------------------------------------
__global__ void vq_finalize_kernel(float* __restrict__ out, int out_size) {
    __shared__ float s_warp[16];
    int tid = threadIdx.x;                 // 512 threads, one partial each
    float v = g_partial[tid];
    #pragma unroll
    for (int off = 16; off >= 1; off >>= 1)
        v += __shfl_xor_sync(0xffffffffu, v, off);
    if ((tid & 31) == 0) s_warp[tid >> 5] = v;
    __syncthreads();
    if (tid == 0) {
        float tot = 0.0f;
        #pragma unroll
        for (int w = 0; w < 16; w++) tot += s_warp[w];
        float mse = tot / (float)((size_t)N_ROWS * DIM);
        float vq_loss = mse * 1.25f;       // embedding + BETA*commitment (equal values)
        if (out_size > N_ROWS * DIM) out[N_ROWS * DIM] = vq_loss;
    }
}

// ---------------------------------------------------------------------------
extern "C" void kernel_launch(void* const* d_in, const int* in_sizes, int n_in,
                              void* d_out, int out_size) {
    const float* lat = (const float*)d_in[0];   // latents [8192, 2048] fp32
    const float* emb = (const float*)d_in[1];   // embedding [1024, 256] fp32
    float* out = (float*)d_out;

    vq_norms_e_kernel<<<(KCODES + 255) / 256, 256>>>(emb);
    vq_norms_x_kernel<<<(N_ROWS * 32 + 255) / 256, 256>>>(lat);
    vq_main_kernel<<<NBLOCKS, 256>>>(lat, emb, out);
    vq_finalize_kernel<<<1, NBLOCKS>>>(out, out_size);
}